// round 10
// baseline (speedup 1.0000x reference)
#include <cuda_runtime.h>
#include <math.h>

#define NB   256
#define LCC  400
#define LQQ  50
#define DD   128
#define ETP  404     // E^T row stride: ET[q][c]
#define XPAD 132     // row stride for P4 xc staging [c][d]
#define QP   52      // q stride for YqT / YqS [d][q]
#define XCS  160     // XcT row stride [d][c], swizzled
#define TP   128     // xq / tmp row stride
#define P1CHUNK 136
#define P4CHUNK 128
#define NT   640

// smem offsets (floats)
#define OFF_ET   0          // 50*404 = 20200
#define OFF_YQT  20200      // 128*52 = 6656  -> sXq (50*128) after P1
#define OFF_YQS  26856      // 128*52 = 6656  -> sTmp (50*128) after P1
#define OFF_XC   33512      // 128*160 = 20480 (P1 XcT swizzled; P4 [c][d] 128*132)
#define OFF_F    53992      // 400
#define OFF_RINV 54392      // 400
#define OFF_CINV 54792      // 64 (slot 63 = scalar M)
#define OFF_QW1  54856      // 64
#define SMEM_FLOATS 54920   // 219680 bytes

#define RES_ELEMS ((size_t)NB * LCC * 4 * DD)

typedef unsigned long long u64;

__device__ __forceinline__ u64 pack2b(float v) {
    u64 r; asm("mov.b64 %0, {%1, %1};" : "=l"(r) : "f"(v)); return r;
}
__device__ __forceinline__ u64 pack2f(float a, float b) {
    u64 r; asm("mov.b64 %0, {%1, %2};" : "=l"(r) : "f"(a), "f"(b)); return r;
}
__device__ __forceinline__ void fma2(u64 &d, u64 a, u64 b) {
    asm("fma.rn.f32x2 %0, %1, %2, %3;" : "=l"(d) : "l"(a), "l"(b), "l"(d));
}
__device__ __forceinline__ void mul2(u64 &d, u64 a, u64 b) {
    asm("mul.rn.f32x2 %0, %1, %2;" : "=l"(d) : "l"(a), "l"(b));
}
__device__ __forceinline__ float2 unpk(u64 v) {
    float2 r; asm("mov.b64 {%0, %1}, %2;" : "=f"(r.x), "=f"(r.y) : "l"(v)); return r;
}

// ---------------- Phase-5 group: NC contiguous c per warp ----------------
template<int NC>
__device__ __forceinline__ void p5_group(
    int c0, int qlen, const float* __restrict__ sET, const float* __restrict__ sXq,
    const float* __restrict__ sTmp, const float* __restrict__ sRInv,
    const float* __restrict__ xcB, float* __restrict__ out, int bLCC, int dg)
{
    u64 A1lo[NC], A1hi[NC], A2lo[NC], A2hi[NC];
    #pragma unroll
    for (int i = 0; i < NC; ++i) { A1lo[i] = 0; A1hi[i] = 0; A2lo[i] = 0; A2hi[i] = 0; }
    #pragma unroll 2
    for (int q = 0; q < qlen; ++q) {
        longlong2 xqv = *(const longlong2*)&sXq[q * TP + dg * 4];
        longlong2 tv  = *(const longlong2*)&sTmp[q * TP + dg * 4];
        #pragma unroll
        for (int g = 0; g < NC / 4; ++g) {
            float4 sa = *(const float4*)&sET[q * ETP + c0 + g * 4];
            const float* sv = (const float*)&sa;
            #pragma unroll
            for (int i = 0; i < 4; ++i) {
                u64 S = pack2b(sv[i]);
                fma2(A1lo[g * 4 + i], S, (u64)xqv.x); fma2(A1hi[g * 4 + i], S, (u64)xqv.y);
                fma2(A2lo[g * 4 + i], S, (u64)tv.x);  fma2(A2hi[g * 4 + i], S, (u64)tv.y);
            }
        }
    }
    #pragma unroll
    for (int i = 0; i < NC; ++i) {
        const int c = c0 + i;
        u64 rv = pack2b(sRInv[c]);
        u64 l1 = A1lo[i], h1 = A1hi[i], l2 = A2lo[i], h2 = A2hi[i];
        mul2(l1, l1, rv); mul2(h1, h1, rv);
        mul2(l2, l2, rv); mul2(h2, h2, rv);
        float4 xcv = *(const float4*)&xcB[(size_t)c * DD + dg * 4];
        float* orow = out + ((size_t)(bLCC + c)) * (4 * DD);
        float2 plo = unpk(l1), phi = unpk(h1);
        float4 A1 = make_float4(plo.x, plo.y, phi.x, phi.y);
        plo = unpk(l2); phi = unpk(h2);
        float4 A2 = make_float4(plo.x, plo.y, phi.x, phi.y);
        *(float4*)&orow[dg * 4] = xcv;
        *(float4*)&orow[DD + dg * 4] = A1;
        float4 m1 = make_float4(xcv.x * A1.x, xcv.y * A1.y, xcv.z * A1.z, xcv.w * A1.w);
        *(float4*)&orow[2 * DD + dg * 4] = m1;
        float4 m2 = make_float4(xcv.x * A2.x, xcv.y * A2.y, xcv.z * A2.z, xcv.w * A2.w);
        *(float4*)&orow[3 * DD + dg * 4] = m2;
    }
}

__global__ __launch_bounds__(NT, 1)
void cqa_kernel(const float* __restrict__ xc_g, const float* __restrict__ xq_g,
                const float* __restrict__ W0, const float* __restrict__ W1,
                const float* __restrict__ W2, const int* __restrict__ clen_g,
                const int* __restrict__ qlen_g, float* __restrict__ out)
{
    extern __shared__ float sm[];
    const int b   = blockIdx.x;
    const int tid = threadIdx.x;
    const float* xcB = xc_g + (size_t)b * LCC * DD;
    const float* xqB = xq_g + (size_t)b * LQQ * DD;
    const int clen = clen_g[b];
    const int qlen = qlen_g[b];

    float* sET   = sm + OFF_ET;
    float* sYqT  = sm + OFF_YQT;
    float* sYqS  = sm + OFF_YQS;
    float* sXq   = sm + OFF_YQT;   // alias: valid after P1
    float* sTmp  = sm + OFF_YQS;   // alias: valid after P1
    float* sXc   = sm + OFF_XC;
    float* sF    = sm + OFF_F;
    float* sRInv = sm + OFF_RINV;
    float* sCInv = sm + OFF_CINV;
    float* sQW1  = sm + OFF_QW1;

    // ---------------- Phase 0: YqT + YqS (pair-swapped) + qW1 ----------------
    if (tid >= LQQ && tid < 64) sQW1[tid] = 0.f;
    for (int d = tid; d < DD; d += NT) {
        sYqT[d * QP + 50] = 0.f; sYqT[d * QP + 51] = 0.f;
        sYqS[d * QP + 50] = 0.f; sYqS[d * QP + 51] = 0.f;
    }
    for (int idx = tid; idx < LQQ * 32; idx += NT) {
        int q  = idx >> 5;
        int c4 = (idx & 31) * 4;
        float4 v  = *(const float4*)&xqB[q * DD + c4];
        float4 w2 = *(const float4*)&W2[c4];
        float4 w0 = *(const float4*)&W0[c4];
        float4 w1 = *(const float4*)&W1[c4];
        float y0 = fmaf(v.x, w2.x, w0.x);
        float y1 = fmaf(v.y, w2.y, w0.y);
        float y2 = fmaf(v.z, w2.z, w0.z);
        float y3 = fmaf(v.w, w2.w, w0.w);
        sYqT[(c4 + 0) * QP + q] = y0;
        sYqT[(c4 + 1) * QP + q] = y1;
        sYqT[(c4 + 2) * QP + q] = y2;
        sYqT[(c4 + 3) * QP + q] = y3;
        int qs = q ^ 1;                       // pair-swapped copy
        sYqS[(c4 + 0) * QP + qs] = y0;
        sYqS[(c4 + 1) * QP + qs] = y1;
        sYqS[(c4 + 2) * QP + qs] = y2;
        sYqS[(c4 + 3) * QP + qs] = y3;
        float s = v.x * w1.x + v.y * w1.y + v.z * w1.z + v.w * w1.w;
        s += __shfl_xor_sync(0xffffffffu, s, 16);
        s += __shfl_xor_sync(0xffffffffu, s, 8);
        s += __shfl_xor_sync(0xffffffffu, s, 4);
        s += __shfl_xor_sync(0xffffffffu, s, 2);
        s += __shfl_xor_sync(0xffffffffu, s, 1);
        if ((idx & 31) == 0) sQW1[q] = s;
    }

    // ---------------- Phase 1: S = qW1 + xc.YqT via swap-permutation FFMA2 ----------------
    // XcT[d][c] swizzled: col = c ^ (d & 28). Chunks 136,136,128.
    for (int cb = 0; cb < LCC; cb += P1CHUNK) {
        const int cn = min(P1CHUNK, LCC - cb);
        __syncthreads();
        // transpose-stage two c-rows per iteration, STS.64 of (x_r, x_{r+1})
        for (int idx = tid; idx < (cn >> 1) * 32; idx += NT) {
            int r2 = idx >> 5;                 // row pair
            int c4 = (idx & 31) * 4;
            int r = r2 * 2;
            float4 va = *(const float4*)&xcB[(size_t)(cb + r) * DD + c4];
            float4 vb = *(const float4*)&xcB[(size_t)(cb + r + 1) * DD + c4];
            const float* fa = (const float*)&va;
            const float* fb = (const float*)&vb;
            #pragma unroll
            for (int j = 0; j < 4; ++j) {
                int d = c4 + j;
                *(float2*)&sXc[d * XCS + (r ^ (d & 28))] = make_float2(fa[j], fb[j]);
            }
        }
        __syncthreads();
        {
            const int qg = tid % 13, cg = tid / 13;
            if (cg < (cn >> 2)) {
                const int q0 = qg * 4, c0l = cg * 4;
                float qw0 = sQW1[q0], qw1 = sQW1[q0 + 1];
                float qw2 = sQW1[q0 + 2], qw3 = sQW1[q0 + 3];
                u64 A000 = pack2f(qw0, qw1), A001 = pack2f(qw1, qw0);
                u64 A010 = pack2f(qw2, qw3), A011 = pack2f(qw3, qw2);
                u64 A100 = A000, A101 = A001, A110 = A010, A111 = A011;
                #pragma unroll 4
                for (int d4 = 0; d4 < DD; d4 += 4) {
                    #pragma unroll
                    for (int dd = 0; dd < 4; ++dd) {
                        const int d = d4 + dd;
                        longlong2 xv = *(const longlong2*)&sXc[d * XCS + (c0l ^ (d & 28))];
                        longlong2 yn = *(const longlong2*)&sYqT[d * QP + q0];
                        longlong2 ys = *(const longlong2*)&sYqS[d * QP + q0];
                        fma2(A000, (u64)xv.x, (u64)yn.x); fma2(A001, (u64)xv.x, (u64)ys.x);
                        fma2(A010, (u64)xv.x, (u64)yn.y); fma2(A011, (u64)xv.x, (u64)ys.y);
                        fma2(A100, (u64)xv.y, (u64)yn.x); fma2(A101, (u64)xv.y, (u64)ys.x);
                        fma2(A110, (u64)xv.y, (u64)yn.y); fma2(A111, (u64)xv.y, (u64)ys.y);
                    }
                }
                const int cgl = cb + c0l;
                float2 a000 = unpk(A000), a001 = unpk(A001);
                float2 a010 = unpk(A010), a011 = unpk(A011);
                float2 a100 = unpk(A100), a101 = unpk(A101);
                float2 a110 = unpk(A110), a111 = unpk(A111);
                *(float4*)&sET[(q0 + 0) * ETP + cgl] = make_float4(a000.x, a001.y, a100.x, a101.y);
                if (q0 + 1 < LQQ)
                    *(float4*)&sET[(q0 + 1) * ETP + cgl] = make_float4(a001.x, a000.y, a101.x, a100.y);
                if (q0 + 2 < LQQ)
                    *(float4*)&sET[(q0 + 2) * ETP + cgl] = make_float4(a010.x, a011.y, a110.x, a111.y);
                if (q0 + 3 < LQQ)
                    *(float4*)&sET[(q0 + 3) * ETP + cgl] = make_float4(a011.x, a010.y, a111.x, a110.y);
            }
        }
    }
    __syncthreads();

    // ---------------- Pass A: per-c masked max, E = exp(S - rmax), masked rsum ----------------
    if (tid < LCC) {
        const int c = tid;
        float m = -3.0e38f;
        #pragma unroll 5
        for (int q = 0; q < LQQ; ++q) {
            float v = sET[q * ETP + c] - (q < qlen ? 0.f : 1e12f);
            m = fmaxf(m, v);
        }
        float sum = 0.f;
        #pragma unroll 5
        for (int q = 0; q < LQQ; ++q) {
            float e = __expf(sET[q * ETP + c] - m);
            sET[q * ETP + c] = e;
            if (q < qlen) sum += e;
        }
        sF[c]    = m;
        sRInv[c] = 1.f / sum;
    }
    __syncthreads();

    // ---------------- M, f[c] ----------------
    if (tid < 32) {
        float m = -3.0e38f;
        for (int c = tid; c < clen; c += 32)
            m = fmaxf(m, sF[c]);
        m = fmaxf(m, __shfl_xor_sync(0xffffffffu, m, 1));
        m = fmaxf(m, __shfl_xor_sync(0xffffffffu, m, 2));
        m = fmaxf(m, __shfl_xor_sync(0xffffffffu, m, 4));
        m = fmaxf(m, __shfl_xor_sync(0xffffffffu, m, 8));
        m = fmaxf(m, __shfl_xor_sync(0xffffffffu, m, 16));
        if (tid == 0) sCInv[63] = m;
    }
    __syncthreads();
    const float Mscal = sCInv[63];
    if (tid < LCC)
        sF[tid] = (tid < clen) ? __expf(sF[tid] - Mscal) : 0.f;
    __syncthreads();

    // ---------------- csum[q] = sum_{c<clen} E[q][c]*f[c] ----------------
    {
        const int g = tid >> 3, s8 = tid & 7;
        float sum = 0.f;
        if (g < LQQ) {
            const float* row = &sET[g * ETP];
            for (int c = s8; c < clen; c += 8)
                sum = fmaf(row[c], sF[c], sum);
        }
        sum += __shfl_xor_sync(0xffffffffu, sum, 1);
        sum += __shfl_xor_sync(0xffffffffu, sum, 2);
        sum += __shfl_xor_sync(0xffffffffu, sum, 4);
        if (g < LQQ && s8 == 0) sCInv[g] = 1.f / sum;
    }
    __syncthreads();

    // ============ Warp-specialized: GEMM warps 0-12 | IO warps 13-19 ============
    const int dg = tid & 31;
    if (tid < 416) {
        // Phase 4: tmp[q,d] = cinv[q]*sum_{c<clen} E[q][c]*(f[c]*xc[c,d])
        const int qg = tid >> 5;
        const int q0 = qg * 4;
        const int qi0 = min(q0 + 0, LQQ - 1), qi1 = min(q0 + 1, LQQ - 1);
        const int qi2 = min(q0 + 2, LQQ - 1), qi3 = min(q0 + 3, LQQ - 1);
        u64 t0lo = 0, t0hi = 0, t1lo = 0, t1hi = 0;
        u64 t2lo = 0, t2hi = 0, t3lo = 0, t3hi = 0;
        for (int cb = 0; cb < clen; cb += P4CHUNK) {
            const int cn = min(P4CHUNK, ((clen - cb) + 3) & ~3);
            asm volatile("bar.sync 1, 416;" ::: "memory");
            for (int idx = tid; idx < cn * 32; idx += 416) {
                int r  = idx >> 5;
                int c4 = (idx & 31) * 4;
                float f = sF[cb + r];
                float4 v = *(const float4*)&xcB[(size_t)(cb + r) * DD + c4];
                v.x *= f; v.y *= f; v.z *= f; v.w *= f;
                *(float4*)&sXc[r * XPAD + c4] = v;
            }
            asm volatile("bar.sync 1, 416;" ::: "memory");
            for (int c = 0; c < cn; c += 4) {
                float4 e0 = *(const float4*)&sET[qi0 * ETP + cb + c];
                float4 e1 = *(const float4*)&sET[qi1 * ETP + cb + c];
                float4 e2 = *(const float4*)&sET[qi2 * ETP + cb + c];
                float4 e3 = *(const float4*)&sET[qi3 * ETP + cb + c];
                const float* f0 = (const float*)&e0;
                const float* f1 = (const float*)&e1;
                const float* f2 = (const float*)&e2;
                const float* f3 = (const float*)&e3;
                #pragma unroll
                for (int cc = 0; cc < 4; ++cc) {
                    longlong2 xv = *(const longlong2*)&sXc[(c + cc) * XPAD + dg * 4];
                    u64 P0 = pack2b(f0[cc]);
                    u64 P1 = pack2b(f1[cc]);
                    u64 P2 = pack2b(f2[cc]);
                    u64 P3 = pack2b(f3[cc]);
                    fma2(t0lo, P0, (u64)xv.x); fma2(t0hi, P0, (u64)xv.y);
                    fma2(t1lo, P1, (u64)xv.x); fma2(t1hi, P1, (u64)xv.y);
                    fma2(t2lo, P2, (u64)xv.x); fma2(t2hi, P2, (u64)xv.y);
                    fma2(t3lo, P3, (u64)xv.x); fma2(t3hi, P3, (u64)xv.y);
                }
            }
        }
        // sTmp aliases YqS (dead after P1) — no extra sync needed before stores
        #define STORE_T(i, LO, HI)                                                \
            if (q0 + (i) < LQQ) {                                                 \
                u64 cv = pack2b(sCInv[q0 + (i)]);                                 \
                u64 lo = LO, hi = HI;                                             \
                mul2(lo, lo, cv); mul2(hi, hi, cv);                               \
                float2 p = unpk(lo);                                              \
                float* trow = &sTmp[(q0 + (i)) * TP + dg * 4];                    \
                trow[0] = p.x; trow[1] = p.y;                                     \
                p = unpk(hi); trow[2] = p.x; trow[3] = p.y;                       \
            }
        STORE_T(0, t0lo, t0hi) STORE_T(1, t1lo, t1hi)
        STORE_T(2, t2lo, t2hi) STORE_T(3, t3lo, t3hi)
        #undef STORE_T
    } else {
        // IO warps (224 threads): stage xq, write S_T and S_bar
        const int wtid = tid - 416;
        for (int idx = wtid; idx < LQQ * 32; idx += 224) {
            int q = idx >> 5, c4 = (idx & 31) * 4;
            *(float4*)&sXq[q * TP + c4] = *(const float4*)&xqB[q * DD + c4];
        }
        float* st_g = out + RES_ELEMS + (size_t)NB * LCC * LQQ + (size_t)b * LQQ * LCC;
        for (int idx = wtid; idx < LQQ * LCC; idx += 224) {
            int q = idx / LCC, c = idx - q * LCC;
            st_g[idx] = sET[q * ETP + c] * sF[c] * sCInv[q];
        }
        float* sbar_g = out + RES_ELEMS + (size_t)b * LCC * LQQ;
        for (int idx = wtid; idx < LCC * LQQ; idx += 224) {
            int c = idx / LQQ, q = idx - c * LQQ;
            float e = (q < qlen) ? sET[q * ETP + c] : 0.f;
            sbar_g[idx] = e * sRInv[c];
        }
    }
    __syncthreads();

    // ---------------- Phase 5: balanced — each warp owns 20 contiguous c ----------------
    {
        const int cg = tid >> 5;               // 0..19
        const int cbase = cg * 20;
        p5_group<8>(cbase,      qlen, sET, sXq, sTmp, sRInv, xcB, out, b * LCC, dg);
        p5_group<8>(cbase + 8,  qlen, sET, sXq, sTmp, sRInv, xcB, out, b * LCC, dg);
        p5_group<4>(cbase + 16, qlen, sET, sXq, sTmp, sRInv, xcB, out, b * LCC, dg);
    }
}

extern "C" void kernel_launch(void* const* d_in, const int* in_sizes, int n_in,
                              void* d_out, int out_size)
{
    const float* xc  = (const float*)d_in[0];
    const float* xq  = (const float*)d_in[1];
    const float* W0  = (const float*)d_in[2];
    const float* W1  = (const float*)d_in[3];
    const float* W2  = (const float*)d_in[4];
    const int* clen  = (const int*)d_in[5];
    const int* qlen  = (const int*)d_in[6];
    float* out = (float*)d_out;

    const int smem_bytes = SMEM_FLOATS * (int)sizeof(float);
    cudaFuncSetAttribute(cqa_kernel, cudaFuncAttributeMaxDynamicSharedMemorySize, smem_bytes);
    cqa_kernel<<<NB, NT, smem_bytes>>>(xc, xq, W0, W1, W2, clen, qlen, out);
}

// round 11
// speedup vs baseline: 1.2224x; 1.2224x over previous
#include <cuda_runtime.h>
#include <math.h>

#define NB   256
#define LCC  400
#define LQQ  50
#define DD   128
#define ETP  404     // E^T row stride: ET[q][c]
#define XPAD 132     // row stride for D-vectors
#define QP   52      // q stride for YqT [d][q]
#define P1CHUNK 200
#define P4CHUNK 128
#define NT   640

// smem offsets (floats)
#define OFF_ET   0          // 50*404 = 20200
#define OFF_YQT  20200      // 128*52 = 6656 -> sTmp (50*132=6600) after P1
#define OFF_XC   26856      // 200*132 = 26400 (P1 staging; P4 rows 0..127; sXq at +16896)
#define OFF_F    53256      // 400
#define OFF_RINV 53656      // 400
#define OFF_CINV 54056      // 64 (slot 63 = scalar M)
#define OFF_QW1  54120      // 64
#define SMEM_FLOATS 54184   // 216736 bytes

#define RES_ELEMS ((size_t)NB * LCC * 4 * DD)

typedef unsigned long long u64;

__device__ __forceinline__ u64 pack2b(float v) {
    u64 r; asm("mov.b64 %0, {%1, %1};" : "=l"(r) : "f"(v)); return r;
}
__device__ __forceinline__ u64 pack2f(float a, float b) {
    u64 r; asm("mov.b64 %0, {%1, %2};" : "=l"(r) : "f"(a), "f"(b)); return r;
}
__device__ __forceinline__ void fma2(u64 &d, u64 a, u64 b) {
    asm("fma.rn.f32x2 %0, %1, %2, %3;" : "=l"(d) : "l"(a), "l"(b), "l"(d));
}
__device__ __forceinline__ void mul2(u64 &d, u64 a, u64 b) {
    asm("mul.rn.f32x2 %0, %1, %2;" : "=l"(d) : "l"(a), "l"(b));
}
__device__ __forceinline__ float2 unpk(u64 v) {
    float2 r; asm("mov.b64 {%0, %1}, %2;" : "=f"(r.x), "=f"(r.y) : "l"(v)); return r;
}

__global__ __launch_bounds__(NT, 1)
void cqa_kernel(const float* __restrict__ xc_g, const float* __restrict__ xq_g,
                const float* __restrict__ W0, const float* __restrict__ W1,
                const float* __restrict__ W2, const int* __restrict__ clen_g,
                const int* __restrict__ qlen_g, float* __restrict__ out)
{
    extern __shared__ float sm[];
    const int b   = blockIdx.x;
    const int tid = threadIdx.x;
    const float* xcB = xc_g + (size_t)b * LCC * DD;
    const float* xqB = xq_g + (size_t)b * LQQ * DD;
    const int clen = clen_g[b];
    const int qlen = qlen_g[b];

    float* sET   = sm + OFF_ET;
    float* sYqT  = sm + OFF_YQT;
    float* sTmp  = sm + OFF_YQT;              // alias: valid after P1
    float* sXc   = sm + OFF_XC;
    float* sXq   = sm + OFF_XC + 16896;       // alias: valid after P1 (P4 staging uses rows 0..127)
    float* sF    = sm + OFF_F;
    float* sRInv = sm + OFF_RINV;
    float* sCInv = sm + OFF_CINV;
    float* sQW1  = sm + OFF_QW1;

    // ---------------- Phase 0: YqT = (xq*W2+W0)^T, qW1 (warp-reduced) ----------------
    if (tid >= LQQ && tid < 64) sQW1[tid] = 0.f;
    for (int d = tid; d < DD; d += NT) {
        sYqT[d * QP + 50] = 0.f;
        sYqT[d * QP + 51] = 0.f;
    }
    for (int idx = tid; idx < LQQ * 32; idx += NT) {
        int q  = idx >> 5;
        int c4 = (idx & 31) * 4;
        float4 v  = *(const float4*)&xqB[q * DD + c4];
        float4 w2 = *(const float4*)&W2[c4];
        float4 w0 = *(const float4*)&W0[c4];
        float4 w1 = *(const float4*)&W1[c4];
        sYqT[(c4 + 0) * QP + q] = fmaf(v.x, w2.x, w0.x);
        sYqT[(c4 + 1) * QP + q] = fmaf(v.y, w2.y, w0.y);
        sYqT[(c4 + 2) * QP + q] = fmaf(v.z, w2.z, w0.z);
        sYqT[(c4 + 3) * QP + q] = fmaf(v.w, w2.w, w0.w);
        float s = v.x * w1.x + v.y * w1.y + v.z * w1.z + v.w * w1.w;
        s += __shfl_xor_sync(0xffffffffu, s, 16);
        s += __shfl_xor_sync(0xffffffffu, s, 8);
        s += __shfl_xor_sync(0xffffffffu, s, 4);
        s += __shfl_xor_sync(0xffffffffu, s, 2);
        s += __shfl_xor_sync(0xffffffffu, s, 1);
        if ((idx & 31) == 0) sQW1[q] = s;
    }

    // ---------------- Phase 1: S = qW1 + xc.YqT ; 2 chunks of 200, 5c x 4q tiles ----------------
    for (int cb = 0; cb < LCC; cb += P1CHUNK) {
        __syncthreads();
        for (int idx = tid; idx < P1CHUNK * 32; idx += NT) {
            int r  = idx >> 5;
            int c4 = (idx & 31) * 4;
            *(float4*)&sXc[r * XPAD + c4] = *(const float4*)&xcB[(size_t)(cb + r) * DD + c4];
        }
        __syncthreads();
        if (tid < 520) {
            const int qg = tid % 13, cg = tid / 13;   // 13 qg x 40 cg
            const int q0 = qg * 4, c0 = cg * 5;
            u64 blo = pack2f(sQW1[q0], sQW1[q0 + 1]);
            u64 bhi = pack2f(sQW1[q0 + 2], sQW1[q0 + 3]);
            u64 a0lo = blo, a0hi = bhi, a1lo = blo, a1hi = bhi;
            u64 a2lo = blo, a2hi = bhi, a3lo = blo, a3hi = bhi;
            u64 a4lo = blo, a4hi = bhi;
            #pragma unroll 4
            for (int d4 = 0; d4 < DD; d4 += 4) {
                float4 x0 = *(const float4*)&sXc[(c0 + 0) * XPAD + d4];
                float4 x1 = *(const float4*)&sXc[(c0 + 1) * XPAD + d4];
                float4 x2 = *(const float4*)&sXc[(c0 + 2) * XPAD + d4];
                float4 x3 = *(const float4*)&sXc[(c0 + 3) * XPAD + d4];
                float4 x4 = *(const float4*)&sXc[(c0 + 4) * XPAD + d4];
                const float* xa0 = (const float*)&x0;
                const float* xa1 = (const float*)&x1;
                const float* xa2 = (const float*)&x2;
                const float* xa3 = (const float*)&x3;
                const float* xa4 = (const float*)&x4;
                #pragma unroll
                for (int dd = 0; dd < 4; ++dd) {
                    longlong2 yv = *(const longlong2*)&sYqT[(d4 + dd) * QP + q0];
                    u64 v0 = pack2b(xa0[dd]);
                    u64 v1 = pack2b(xa1[dd]);
                    u64 v2 = pack2b(xa2[dd]);
                    u64 v3 = pack2b(xa3[dd]);
                    u64 v4 = pack2b(xa4[dd]);
                    fma2(a0lo, v0, (u64)yv.x); fma2(a0hi, v0, (u64)yv.y);
                    fma2(a1lo, v1, (u64)yv.x); fma2(a1hi, v1, (u64)yv.y);
                    fma2(a2lo, v2, (u64)yv.x); fma2(a2hi, v2, (u64)yv.y);
                    fma2(a3lo, v3, (u64)yv.x); fma2(a3hi, v3, (u64)yv.y);
                    fma2(a4lo, v4, (u64)yv.x); fma2(a4hi, v4, (u64)yv.y);
                }
            }
            // transpose-store to ET (5 scalar stores per q row)
            const int cgl = cb + c0;
            float2 p0 = unpk(a0lo), p1 = unpk(a1lo), p2 = unpk(a2lo), p3 = unpk(a3lo), p4 = unpk(a4lo);
            {
                float* r0 = &sET[(q0 + 0) * ETP + cgl];
                r0[0] = p0.x; r0[1] = p1.x; r0[2] = p2.x; r0[3] = p3.x; r0[4] = p4.x;
            }
            if (q0 + 1 < LQQ) {
                float* r1 = &sET[(q0 + 1) * ETP + cgl];
                r1[0] = p0.y; r1[1] = p1.y; r1[2] = p2.y; r1[3] = p3.y; r1[4] = p4.y;
            }
            p0 = unpk(a0hi); p1 = unpk(a1hi); p2 = unpk(a2hi); p3 = unpk(a3hi); p4 = unpk(a4hi);
            if (q0 + 2 < LQQ) {
                float* r2 = &sET[(q0 + 2) * ETP + cgl];
                r2[0] = p0.x; r2[1] = p1.x; r2[2] = p2.x; r2[3] = p3.x; r2[4] = p4.x;
            }
            if (q0 + 3 < LQQ) {
                float* r3 = &sET[(q0 + 3) * ETP + cgl];
                r3[0] = p0.y; r3[1] = p1.y; r3[2] = p2.y; r3[3] = p3.y; r3[4] = p4.y;
            }
        }
    }
    __syncthreads();

    // ---------------- Pass A: per-c masked max, E = exp(S - rmax), masked rsum ----------------
    if (tid < LCC) {
        const int c = tid;
        float m = -3.0e38f;
        #pragma unroll 5
        for (int q = 0; q < LQQ; ++q) {
            float v = sET[q * ETP + c] - (q < qlen ? 0.f : 1e12f);
            m = fmaxf(m, v);
        }
        float sum = 0.f;
        #pragma unroll 5
        for (int q = 0; q < LQQ; ++q) {
            float e = __expf(sET[q * ETP + c] - m);
            sET[q * ETP + c] = e;
            if (q < qlen) sum += e;
        }
        sF[c]    = m;
        sRInv[c] = 1.f / sum;
    }
    __syncthreads();

    // ---------------- M = max_{c<clen} rmax[c];  f[c] = exp(rmax[c]-M), 0 for c>=clen ----------------
    if (tid < 32) {
        float m = -3.0e38f;
        for (int c = tid; c < clen; c += 32)
            m = fmaxf(m, sF[c]);
        m = fmaxf(m, __shfl_xor_sync(0xffffffffu, m, 1));
        m = fmaxf(m, __shfl_xor_sync(0xffffffffu, m, 2));
        m = fmaxf(m, __shfl_xor_sync(0xffffffffu, m, 4));
        m = fmaxf(m, __shfl_xor_sync(0xffffffffu, m, 8));
        m = fmaxf(m, __shfl_xor_sync(0xffffffffu, m, 16));
        if (tid == 0) sCInv[63] = m;
    }
    __syncthreads();
    const float Mscal = sCInv[63];
    if (tid < LCC)
        sF[tid] = (tid < clen) ? __expf(sF[tid] - Mscal) : 0.f;
    __syncthreads();

    // ---------------- csum[q] = sum_{c<clen} E[q][c]*f[c] ----------------
    {
        const int g = tid >> 3, s8 = tid & 7;
        float sum = 0.f;
        if (g < LQQ) {
            const float* row = &sET[g * ETP];
            for (int c = s8; c < clen; c += 8)
                sum = fmaf(row[c], sF[c], sum);
        }
        sum += __shfl_xor_sync(0xffffffffu, sum, 1);
        sum += __shfl_xor_sync(0xffffffffu, sum, 2);
        sum += __shfl_xor_sync(0xffffffffu, sum, 4);
        if (g < LQQ && s8 == 0) sCInv[g] = 1.f / sum;
    }
    __syncthreads();

    // ============ Warp-specialized: GEMM warps 0-12 | IO warps 13-19 ============
    const int dg = tid & 31;
    if (tid < 416) {
        // Phase 4: tmp[q,d] = cinv[q]*sum_{c<clen} E[q][c]*(f[c]*xc[c,d]); skip q0 >= qlen
        const int qg = tid >> 5;
        const int q0 = qg * 4;
        const bool act = (q0 < qlen);
        const int qi0 = min(q0 + 0, LQQ - 1), qi1 = min(q0 + 1, LQQ - 1);
        const int qi2 = min(q0 + 2, LQQ - 1), qi3 = min(q0 + 3, LQQ - 1);
        u64 t0lo = 0, t0hi = 0, t1lo = 0, t1hi = 0;
        u64 t2lo = 0, t2hi = 0, t3lo = 0, t3hi = 0;
        for (int cb = 0; cb < clen; cb += P4CHUNK) {
            const int cn = min(P4CHUNK, ((clen - cb) + 3) & ~3);
            asm volatile("bar.sync 1, 416;" ::: "memory");
            for (int idx = tid; idx < cn * 32; idx += 416) {
                int r  = idx >> 5;
                int c4 = (idx & 31) * 4;
                float f = sF[cb + r];
                float4 v = *(const float4*)&xcB[(size_t)(cb + r) * DD + c4];
                v.x *= f; v.y *= f; v.z *= f; v.w *= f;
                *(float4*)&sXc[r * XPAD + c4] = v;
            }
            asm volatile("bar.sync 1, 416;" ::: "memory");
            if (act) {
                for (int c = 0; c < cn; c += 4) {
                    float4 e0 = *(const float4*)&sET[qi0 * ETP + cb + c];
                    float4 e1 = *(const float4*)&sET[qi1 * ETP + cb + c];
                    float4 e2 = *(const float4*)&sET[qi2 * ETP + cb + c];
                    float4 e3 = *(const float4*)&sET[qi3 * ETP + cb + c];
                    const float* f0 = (const float*)&e0;
                    const float* f1 = (const float*)&e1;
                    const float* f2 = (const float*)&e2;
                    const float* f3 = (const float*)&e3;
                    #pragma unroll
                    for (int cc = 0; cc < 4; ++cc) {
                        longlong2 xv = *(const longlong2*)&sXc[(c + cc) * XPAD + dg * 4];
                        u64 P0 = pack2b(f0[cc]);
                        u64 P1 = pack2b(f1[cc]);
                        u64 P2 = pack2b(f2[cc]);
                        u64 P3 = pack2b(f3[cc]);
                        fma2(t0lo, P0, (u64)xv.x); fma2(t0hi, P0, (u64)xv.y);
                        fma2(t1lo, P1, (u64)xv.x); fma2(t1hi, P1, (u64)xv.y);
                        fma2(t2lo, P2, (u64)xv.x); fma2(t2hi, P2, (u64)xv.y);
                        fma2(t3lo, P3, (u64)xv.x); fma2(t3hi, P3, (u64)xv.y);
                    }
                }
            }
        }
        // sTmp aliases YqT (dead after P1) — disjoint from sXc staging, no extra sync
        #define STORE_T(i, LO, HI)                                                \
            if (q0 + (i) < qlen) {                                                \
                u64 cv = pack2b(sCInv[q0 + (i)]);                                 \
                u64 lo = LO, hi = HI;                                             \
                mul2(lo, lo, cv); mul2(hi, hi, cv);                               \
                float2 p = unpk(lo);                                              \
                float* trow = &sTmp[(q0 + (i)) * XPAD + dg * 4];                  \
                trow[0] = p.x; trow[1] = p.y;                                     \
                p = unpk(hi); trow[2] = p.x; trow[3] = p.y;                       \
            }
        STORE_T(0, t0lo, t0hi) STORE_T(1, t1lo, t1hi)
        STORE_T(2, t2lo, t2hi) STORE_T(3, t3lo, t3hi)
        #undef STORE_T
    } else {
        // ---------------- IO warps (7 warps, 224 threads), vectorized ----------------
        const int wtid = tid - 416;
        // stage xq
        for (int idx = wtid; idx < LQQ * 32; idx += 224) {
            int q = idx >> 5, c4 = (idx & 31) * 4;
            *(float4*)&sXq[q * XPAD + c4] = *(const float4*)&xqB[q * DD + c4];
        }
        // S_T out (float4 over c): st[q][c] = E[q][c]*f[c]*cinv[q]
        float* st_g = out + RES_ELEMS + (size_t)NB * LCC * LQQ + (size_t)b * LQQ * LCC;
        for (int idx = wtid; idx < LQQ * (LCC / 4); idx += 224) {
            int q = idx / (LCC / 4), c4 = (idx - q * (LCC / 4)) * 4;
            float4 e = *(const float4*)&sET[q * ETP + c4];
            float4 f = *(const float4*)&sF[c4];
            float cv = sCInv[q];
            float4 r = make_float4(e.x * f.x * cv, e.y * f.y * cv,
                                   e.z * f.z * cv, e.w * f.w * cv);
            *(float4*)&st_g[q * LCC + c4] = r;
        }
        // S_bar out (float2 over q): sbar[c][q] = (q<qlen ? E : 0) * rinv[c]
        float* sbar_g = out + RES_ELEMS + (size_t)b * LCC * LQQ;
        for (int idx = wtid; idx < LCC * (LQQ / 2); idx += 224) {
            int c = idx / (LQQ / 2), q = (idx - c * (LQQ / 2)) * 2;
            float rv = sRInv[c];
            float e0 = (q < qlen) ? sET[q * ETP + c] : 0.f;
            float e1 = (q + 1 < qlen) ? sET[(q + 1) * ETP + c] : 0.f;
            *(float2*)&sbar_g[c * LQQ + q] = make_float2(e0 * rv, e1 * rv);
        }
    }
    __syncthreads();

    // ---------------- Phase 5: c2q = (E*rinv)@xq, q2c = (E*rinv)@tmp, fused epilogue ----------------
    {
        const int cg = tid >> 5;                   // 0..19
        for (int cb = 0; cb < LCC; cb += 160) {
            const int c0 = cb + cg * 8;
            if (c0 >= LCC) continue;
            u64 A1lo[8], A1hi[8], A2lo[8], A2hi[8];
            #pragma unroll
            for (int i = 0; i < 8; ++i) { A1lo[i] = 0; A1hi[i] = 0; A2lo[i] = 0; A2hi[i] = 0; }
            #pragma unroll 2
            for (int q = 0; q < qlen; ++q) {
                longlong2 xqv = *(const longlong2*)&sXq[q * XPAD + dg * 4];
                longlong2 tv  = *(const longlong2*)&sTmp[q * XPAD + dg * 4];
                float4 sa = *(const float4*)&sET[q * ETP + c0];
                float4 sb = *(const float4*)&sET[q * ETP + c0 + 4];
                const float* sv0 = (const float*)&sa;
                const float* sv1 = (const float*)&sb;
                #pragma unroll
                for (int i = 0; i < 4; ++i) {
                    u64 S = pack2b(sv0[i]);
                    fma2(A1lo[i], S, (u64)xqv.x); fma2(A1hi[i], S, (u64)xqv.y);
                    fma2(A2lo[i], S, (u64)tv.x);  fma2(A2hi[i], S, (u64)tv.y);
                }
                #pragma unroll
                for (int i = 0; i < 4; ++i) {
                    u64 S = pack2b(sv1[i]);
                    fma2(A1lo[4 + i], S, (u64)xqv.x); fma2(A1hi[4 + i], S, (u64)xqv.y);
                    fma2(A2lo[4 + i], S, (u64)tv.x);  fma2(A2hi[4 + i], S, (u64)tv.y);
                }
            }
            #pragma unroll
            for (int i = 0; i < 8; ++i) {
                const int c = c0 + i;
                u64 rv = pack2b(sRInv[c]);
                u64 l1 = A1lo[i], h1 = A1hi[i], l2 = A2lo[i], h2 = A2hi[i];
                mul2(l1, l1, rv); mul2(h1, h1, rv);
                mul2(l2, l2, rv); mul2(h2, h2, rv);
                float4 xcv = *(const float4*)&xcB[(size_t)c * DD + dg * 4];
                float* orow = out + ((size_t)(b * LCC + c)) * (4 * DD);
                float2 plo = unpk(l1), phi = unpk(h1);
                float4 A1 = make_float4(plo.x, plo.y, phi.x, phi.y);
                plo = unpk(l2); phi = unpk(h2);
                float4 A2 = make_float4(plo.x, plo.y, phi.x, phi.y);
                *(float4*)&orow[dg * 4] = xcv;
                *(float4*)&orow[DD + dg * 4] = A1;
                float4 m1 = make_float4(xcv.x * A1.x, xcv.y * A1.y,
                                        xcv.z * A1.z, xcv.w * A1.w);
                *(float4*)&orow[2 * DD + dg * 4] = m1;
                float4 m2 = make_float4(xcv.x * A2.x, xcv.y * A2.y,
                                        xcv.z * A2.z, xcv.w * A2.w);
                *(float4*)&orow[3 * DD + dg * 4] = m2;
            }
        }
    }
}

extern "C" void kernel_launch(void* const* d_in, const int* in_sizes, int n_in,
                              void* d_out, int out_size)
{
    const float* xc  = (const float*)d_in[0];
    const float* xq  = (const float*)d_in[1];
    const float* W0  = (const float*)d_in[2];
    const float* W1  = (const float*)d_in[3];
    const float* W2  = (const float*)d_in[4];
    const int* clen  = (const int*)d_in[5];
    const int* qlen  = (const int*)d_in[6];
    float* out = (float*)d_out;

    const int smem_bytes = SMEM_FLOATS * (int)sizeof(float);
    cudaFuncSetAttribute(cqa_kernel, cudaFuncAttributeMaxDynamicSharedMemorySize, smem_bytes);
    cqa_kernel<<<NB, NT, smem_bytes>>>(xc, xq, W0, W1, W2, clen, qlen, out);
}